// round 10
// baseline (speedup 1.0000x reference)
#include <cuda_runtime.h>
#include <cstdint>

#define L      8192
#define F      9
#define NT     1024
#define CH     8                 // tiles (rows per thread)
#define PL     9216              // padded scan length: L + L/8  (== TFLOAT)
#define TFLOAT 9216              // floats per tile = NT * F
#define TBYTES 36864             // bytes per tile
#define NBUF   4

__device__ __forceinline__ int pidx(int t) { return t + (t >> 3); }
__device__ __forceinline__ float clip01(float x) { return fminf(fmaxf(x, 0.0f), 0.9999f); }

__device__ __forceinline__ uint32_t smem_u32(const void* p) {
    uint32_t a;
    asm("{ .reg .u64 t; cvta.to.shared.u64 t, %1; cvt.u32.u64 %0, t; }" : "=r"(a) : "l"(p));
    return a;
}
__device__ __forceinline__ void mbar_init(uint32_t mbar, uint32_t cnt) {
    asm volatile("mbarrier.init.shared.b64 [%0], %1;" :: "r"(mbar), "r"(cnt) : "memory");
}
__device__ __forceinline__ void mbar_expect_tx(uint32_t mbar, uint32_t bytes) {
    asm volatile("mbarrier.arrive.expect_tx.shared.b64 _, [%0], %1;" :: "r"(mbar), "r"(bytes) : "memory");
}
__device__ __forceinline__ void bulk_g2s(uint32_t dst, const float* src, uint32_t bytes, uint32_t mbar) {
    asm volatile("cp.async.bulk.shared::cta.global.mbarrier::complete_tx::bytes [%0], [%1], %2, [%3];"
                 :: "r"(dst), "l"(src), "r"(bytes), "r"(mbar) : "memory");
}
__device__ __forceinline__ void mbar_wait_acq(uint32_t mbar, uint32_t parity) {
    asm volatile(
        "{\n\t.reg .pred P;\n\t"
        "W_%=:\n\t"
        "mbarrier.try_wait.parity.acquire.cta.shared::cta.b64 P, [%0], %1, 0x989680;\n\t"
        "@P bra.uni D_%=;\n\t"
        "bra.uni W_%=;\n\t"
        "D_%=:\n\t}"
        :: "r"(mbar), "r"(parity) : "memory");
}

__global__ __launch_bounds__(NT, 1)
void kenneth_kernel(const float* __restrict__ conc,
                    const float* __restrict__ kern,
                    float* __restrict__ out) {
    extern __shared__ float sm[];
    float* sb  = sm;                 // bcd (padded)
    float* sp  = sm + PL;            // rowsum -> P (padded)
    float* stg = sm + 2 * PL;        // 4 stage buffers of TFLOAT
    float* qf  = stg;                // Q_f reuses stage buf 0 (after Phase A)
    float* qb  = stg + TFLOAT;       // Q_b reuses stage buf 1
    __shared__ float wredp[32], wredf[32], wredb[32];
    __shared__ float sZ1;
    __shared__ uint64_t full_s[NBUF];
    __shared__ int cnt[NBUF];

    const int tid  = threadIdx.x;
    const int lane = tid & 31;
    const int wid  = tid >> 5;
    const float k  = kern[0];
    const float* gin = conc + (size_t)blockIdx.x * (L * F);
    float* outb = out + (size_t)blockIdx.x * (F * L);

    uint32_t full_a = smem_u32(&full_s[0]);
    uint32_t stg_a  = smem_u32(stg);

    // ---- Init mbarriers + counters, launch 4-deep DMA pipeline ----
    if (tid == 0) {
#pragma unroll
        for (int b = 0; b < NBUF; b++) {
            mbar_init(full_a + 8 * b, 1);
            cnt[b] = 0;
        }
    }
    __syncthreads();
    if (tid == 0) {
#pragma unroll
        for (int b = 0; b < NBUF; b++) {
            mbar_expect_tx(full_a + 8 * b, TBYTES);
            bulk_g2s(stg_a + b * TBYTES, gin + b * TFLOAT, TBYTES, full_a + 8 * b);
        }
    }

    // ---- Phase Z: Z1 = 1 + sum(all inputs); overlaps the in-flight DMAs ----
    {
        const float4* g4 = reinterpret_cast<const float4*>(gin);
        float tot = 0.0f;
#pragma unroll
        for (int g = 0; g < 18; g++) {
            float4 q = g4[g * NT + tid];
            tot += (q.x + q.y) + (q.z + q.w);
        }
#pragma unroll
        for (int d = 16; d >= 1; d >>= 1) tot += __shfl_xor_sync(0xFFFFFFFFu, tot, d);
        if (lane == 0) wredp[wid] = tot;
        __syncthreads();
        if (wid == 0) {
            float s = wredp[lane];
#pragma unroll
            for (int d = 16; d >= 1; d >>= 1) s += __shfl_xor_sync(0xFFFFFFFFu, s, d);
            if (lane == 0) sZ1 = 1.0f + s;
        }
        __syncthreads();
    }
    const float Z1 = sZ1;
    const float C2 = Z1 + 1.0f;
    const float invZ1 = 1.0f / Z1;

    // ---- Phase A: fully barrier-free pipelined tiles ----
    // Consumption tracked by smem atomics; the LAST warp to finish a buffer
    // issues its refill DMA. No thread ever blocks on other warps.
    float bcd[CH];
#pragma unroll
    for (int ii = 0; ii < CH; ii++) {
        const int b = ii & 3;
        float* sbuf = stg + b * TFLOAT;
        mbar_wait_acq(full_a + 8 * b, (ii >> 2) & 1);

        float v[9];
#pragma unroll
        for (int c = 0; c < 9; c++) v[c] = sbuf[9 * tid + c];

        int t = ii * NT + tid;
        float bv = v[0];
        float acc = ((v[1] + v[2]) + (v[3] + v[4]))
                  + ((v[5] + v[6]) + (v[7] + v[8])) + v[0];
        bcd[ii] = bv;
        sb[pidx(t)] = bv;
        sp[pidx(t)] = acc;

#pragma unroll
        for (int c = 1; c < 9; c++) {
            float vv = v[c];
            float u = (vv > 1e-13f) ? vv : (vv * vv) / (vv + 1.0f);
            outb[(size_t)c * L + t] = clip01(u * invZ1);
        }

        if (ii < CH - NBUF) {
            // all of this warp's lanes have consumed buffer b (values already
            // used by the dependent stores above)
            __syncwarp();
            if (lane == 0) {
                int old = atomicAdd(&cnt[b], 1);
                if (old == 31) {   // last warp: refill buffer b with tile ii+4
                    mbar_expect_tx(full_a + 8 * b, TBYTES);
                    bulk_g2s(stg_a + b * TBYTES, gin + (ii + NBUF) * TFLOAT,
                             TBYTES, full_a + 8 * b);
                }
            }
        }
    }
    __syncthreads();

    // ---- Phase B: P = 1 + inclusive cumsum(rowsum), chunked ownership ----
    const int base = CH * tid;
    {
        float pv[CH];
        float run = 0.0f;
#pragma unroll
        for (int j = 0; j < CH; j++) { run += sp[pidx(base + j)]; pv[j] = run; }
        float x = run;
#pragma unroll
        for (int d = 1; d < 32; d <<= 1) {
            float y = __shfl_up_sync(0xFFFFFFFFu, x, d);
            if (lane >= d) x += y;
        }
        if (lane == 31) wredp[wid] = x;
        __syncthreads();
        if (wid == 0) {
            float w = wredp[lane];
#pragma unroll
            for (int d = 1; d < 32; d <<= 1) {
                float y = __shfl_up_sync(0xFFFFFFFFu, w, d);
                if (lane >= d) w += y;
            }
            wredp[lane] = w;
        }
        __syncthreads();
        float off = 1.0f + (x - run) + (wid > 0 ? wredp[wid - 1] : 0.0f);
#pragma unroll
        for (int j = 0; j < CH; j++) sp[pidx(base + j)] = off + pv[j];
    }
    __syncthreads();

    // ---- Phase C: build q_f/q_b and fused dual scan (overwrites stage bufs 0/1) ----
    {
        float qfv[CH], qbv[CH];
#pragma unroll
        for (int j = 0; j < CH; j++) {
            int i = base + j;
            float bv = sb[pidx(i)];
            float pf = (i >= 14)    ? sp[pidx(i - 14)]        : 1.0f;
            float sv = (i + 14 < L) ? (C2 - sp[pidx(i + 13)]) : 1.0f;
            qfv[j] = bv * pf;
            qbv[j] = bv * sv;
        }
#pragma unroll
        for (int j = 1; j < CH; j++) { qfv[j] += qfv[j - 1]; qbv[j] += qbv[j - 1]; }
        float tf = qfv[CH - 1], tb = qbv[CH - 1];
        float xf = tf, xb = tb;
#pragma unroll
        for (int d = 1; d < 32; d <<= 1) {
            float yf = __shfl_up_sync(0xFFFFFFFFu, xf, d);
            float yb = __shfl_up_sync(0xFFFFFFFFu, xb, d);
            if (lane >= d) { xf += yf; xb += yb; }
        }
        if (lane == 31) { wredf[wid] = xf; wredb[wid] = xb; }
        __syncthreads();
        if (wid == 0) {
            float wf = wredf[lane], wb = wredb[lane];
#pragma unroll
            for (int d = 1; d < 32; d <<= 1) {
                float yf = __shfl_up_sync(0xFFFFFFFFu, wf, d);
                float yb = __shfl_up_sync(0xFFFFFFFFu, wb, d);
                if (lane >= d) { wf += yf; wb += yb; }
            }
            wredf[lane] = wf; wredb[lane] = wb;
        }
        __syncthreads();
        float offf = (xf - tf) + (wid > 0 ? wredf[wid - 1] : 0.0f);
        float offb = (xb - tb) + (wid > 0 ? wredb[wid - 1] : 0.0f);
#pragma unroll
        for (int j = 0; j < CH; j++) {
            qf[pidx(base + j)] = offf + qfv[j];
            qb[pidx(base + j)] = offb + qbv[j];
        }
    }
    __syncthreads();

    // ---- Phase D: channel 0 (windows), strided, coalesced, division-free ----
    const float bI = invZ1;
    const float kI = k * invZ1;
#pragma unroll
    for (int ii = 0; ii < CH; ii++) {
        int t = ii * NT + tid;
        float bv = bcd[ii];
        float wfv = ((t >= 16) ? qf[pidx(t - 16)] : 0.0f)
                  - ((t >= 76) ? qf[pidx(t - 76)] : 0.0f);
        int hi = t + 75; if (hi > L - 1) hi = L - 1;
        int lo = t + 15; if (lo > L - 1) lo = L - 1;
        float wbv = qb[pidx(hi)] - qb[pidx(lo)];
        float w = wfv + wbv;
        float o = fmaf(bv * kI, w, bv * bI);         // b>eps fast path
        if (!(bv > 1e-13f)) {
            float t0 = fmaf(k, w, 1.0f);
            o = (bv * bv * t0) / (bv + 1.0f) * invZ1;
        }
        outb[t] = clip01(o);
    }
}

extern "C" void kernel_launch(void* const* d_in, const int* in_sizes, int n_in,
                              void* d_out, int out_size) {
    const float* conc = (const float*)d_in[0];
    const float* kern = (const float*)d_in[1];
    float* out = (float*)d_out;
    const int B = in_sizes[0] / (L * F);

    const size_t smem = (size_t)(2 * PL + NBUF * TFLOAT) * sizeof(float);  // 221,184 B
    cudaFuncSetAttribute(kenneth_kernel,
                         cudaFuncAttributeMaxDynamicSharedMemorySize, (int)smem);
    kenneth_kernel<<<B, NT, smem>>>(conc, kern, out);
}

// round 11
// speedup vs baseline: 1.3668x; 1.3668x over previous
#include <cuda_runtime.h>
#include <cstdint>

#define L      8192
#define F      9
#define NT     1024
#define CH     8                 // tiles (rows per thread)
#define PL     9216              // padded scan length: L + L/8  (== TFLOAT)
#define TFLOAT 9216              // floats per tile = NT * F
#define TBYTES 36864             // bytes per tile
#define NBUF   4

__device__ __forceinline__ int pidx(int t) { return t + (t >> 3); }
__device__ __forceinline__ float clip01(float x) { return fminf(fmaxf(x, 0.0f), 0.9999f); }

__device__ __forceinline__ uint32_t smem_u32(const void* p) {
    uint32_t a;
    asm("{ .reg .u64 t; cvta.to.shared.u64 t, %1; cvt.u32.u64 %0, t; }" : "=r"(a) : "l"(p));
    return a;
}
__device__ __forceinline__ void mbar_init(uint32_t mbar, uint32_t cnt) {
    asm volatile("mbarrier.init.shared.b64 [%0], %1;" :: "r"(mbar), "r"(cnt) : "memory");
}
__device__ __forceinline__ void mbar_expect_tx(uint32_t mbar, uint32_t bytes) {
    asm volatile("mbarrier.arrive.expect_tx.shared.b64 _, [%0], %1;" :: "r"(mbar), "r"(bytes) : "memory");
}
__device__ __forceinline__ void bulk_g2s(uint32_t dst, const float* src, uint32_t bytes, uint32_t mbar) {
    asm volatile("cp.async.bulk.shared::cta.global.mbarrier::complete_tx::bytes [%0], [%1], %2, [%3];"
                 :: "r"(dst), "l"(src), "r"(bytes), "r"(mbar) : "memory");
}
__device__ __forceinline__ void mbar_wait_acq(uint32_t mbar, uint32_t parity) {
    asm volatile(
        "{\n\t.reg .pred P;\n\t"
        "W_%=:\n\t"
        "mbarrier.try_wait.parity.acquire.cta.shared::cta.b64 P, [%0], %1, 0x989680;\n\t"
        "@P bra.uni D_%=;\n\t"
        "bra.uni W_%=;\n\t"
        "D_%=:\n\t}"
        :: "r"(mbar), "r"(parity) : "memory");
}

__global__ __launch_bounds__(NT, 1)
void kenneth_kernel(const float* __restrict__ conc,
                    const float* __restrict__ kern,
                    float* __restrict__ out) {
    extern __shared__ float sm[];
    float* sb  = sm;                 // bcd (padded)
    float* sp  = sm + PL;            // rowsum -> P (padded)
    float* stg = sm + 2 * PL;        // 4 stage buffers of TFLOAT
    float* qf  = stg;                // Q_f reuses stage buf 0 (after Phase A)
    float* qb  = stg + TFLOAT;       // Q_b reuses stage buf 1
    __shared__ float wredp[32], wredf[32], wredb[32];
    __shared__ float sZ1;
    __shared__ uint64_t full_s[NBUF];

    const int tid  = threadIdx.x;
    const int lane = tid & 31;
    const int wid  = tid >> 5;
    const float k  = kern[0];
    const float* gin = conc + (size_t)blockIdx.x * (L * F);
    float* outb = out + (size_t)blockIdx.x * (F * L);

    uint32_t full_a = smem_u32(&full_s[0]);
    uint32_t stg_a  = smem_u32(stg);

    // ---- Init mbarriers, launch all 4 first-half DMAs ----
    if (tid == 0) {
#pragma unroll
        for (int b = 0; b < NBUF; b++) mbar_init(full_a + 8 * b, 1);
    }
    __syncthreads();
    if (tid == 0) {
#pragma unroll
        for (int b = 0; b < NBUF; b++) {
            mbar_expect_tx(full_a + 8 * b, TBYTES);
            bulk_g2s(stg_a + b * TBYTES, gin + b * TFLOAT, TBYTES, full_a + 8 * b);
        }
    }

    // ---- Phase Z: Z1 = 1 + sum(all inputs); overlaps the in-flight DMAs ----
    {
        const float4* g4 = reinterpret_cast<const float4*>(gin);
        float tot = 0.0f;
#pragma unroll
        for (int g = 0; g < 18; g++) {
            float4 q = g4[g * NT + tid];
            tot += (q.x + q.y) + (q.z + q.w);
        }
#pragma unroll
        for (int d = 16; d >= 1; d >>= 1) tot += __shfl_xor_sync(0xFFFFFFFFu, tot, d);
        if (lane == 0) wredp[wid] = tot;
        __syncthreads();
        if (wid == 0) {
            float s = wredp[lane];
#pragma unroll
            for (int d = 16; d >= 1; d >>= 1) s += __shfl_xor_sync(0xFFFFFFFFu, s, d);
            if (lane == 0) sZ1 = 1.0f + s;
        }
        __syncthreads();
    }
    const float Z1 = sZ1;
    const float C2 = Z1 + 1.0f;
    const float invZ1 = 1.0f / Z1;

    // ---- Phase A: 8 tiles, ONE block barrier total ----
    // Tiles 0-3: each warp self-paced, gated only by its DMA full-barrier.
    // One __syncthreads proves buffers 0-3 fully consumed; tid0 issues all 4
    // refills; tiles 4-7 again self-paced.
    float bcd[CH];
#pragma unroll
    for (int ii = 0; ii < CH; ii++) {
        const int b = ii & 3;
        float* sbuf = stg + b * TFLOAT;
        mbar_wait_acq(full_a + 8 * b, (ii >> 2) & 1);

        float v[9];
#pragma unroll
        for (int c = 0; c < 9; c++) v[c] = sbuf[9 * tid + c];

        int t = ii * NT + tid;
        float bv = v[0];
        float acc = ((v[1] + v[2]) + (v[3] + v[4]))
                  + ((v[5] + v[6]) + (v[7] + v[8])) + v[0];
        bcd[ii] = bv;
        sb[pidx(t)] = bv;
        sp[pidx(t)] = acc;

#pragma unroll
        for (int c = 1; c < 9; c++) {
            float vv = v[c];
            float u = (vv > 1e-13f) ? vv : (vv * vv) / (vv + 1.0f);
            outb[(size_t)c * L + t] = clip01(u * invZ1);
        }

        if (ii == 3) {
            __syncthreads();          // buffers 0-3 consumed by ALL warps
            if (tid == 0) {
#pragma unroll
                for (int b2 = 0; b2 < NBUF; b2++) {
                    mbar_expect_tx(full_a + 8 * b2, TBYTES);
                    bulk_g2s(stg_a + b2 * TBYTES, gin + (4 + b2) * TFLOAT,
                             TBYTES, full_a + 8 * b2);
                }
            }
        }
    }
    __syncthreads();

    // ---- Phase B: P = 1 + inclusive cumsum(rowsum), chunked ownership ----
    const int base = CH * tid;
    {
        float pv[CH];
        float run = 0.0f;
#pragma unroll
        for (int j = 0; j < CH; j++) { run += sp[pidx(base + j)]; pv[j] = run; }
        float x = run;
#pragma unroll
        for (int d = 1; d < 32; d <<= 1) {
            float y = __shfl_up_sync(0xFFFFFFFFu, x, d);
            if (lane >= d) x += y;
        }
        if (lane == 31) wredp[wid] = x;
        __syncthreads();
        if (wid == 0) {
            float w = wredp[lane];
#pragma unroll
            for (int d = 1; d < 32; d <<= 1) {
                float y = __shfl_up_sync(0xFFFFFFFFu, w, d);
                if (lane >= d) w += y;
            }
            wredp[lane] = w;
        }
        __syncthreads();
        float off = 1.0f + (x - run) + (wid > 0 ? wredp[wid - 1] : 0.0f);
#pragma unroll
        for (int j = 0; j < CH; j++) sp[pidx(base + j)] = off + pv[j];
    }
    __syncthreads();

    // ---- Phase C: build q_f/q_b and fused dual scan (overwrites stage bufs 0/1) ----
    {
        float qfv[CH], qbv[CH];
#pragma unroll
        for (int j = 0; j < CH; j++) {
            int i = base + j;
            float bv = sb[pidx(i)];
            float pf = (i >= 14)    ? sp[pidx(i - 14)]        : 1.0f;
            float sv = (i + 14 < L) ? (C2 - sp[pidx(i + 13)]) : 1.0f;
            qfv[j] = bv * pf;
            qbv[j] = bv * sv;
        }
#pragma unroll
        for (int j = 1; j < CH; j++) { qfv[j] += qfv[j - 1]; qbv[j] += qbv[j - 1]; }
        float tf = qfv[CH - 1], tb = qbv[CH - 1];
        float xf = tf, xb = tb;
#pragma unroll
        for (int d = 1; d < 32; d <<= 1) {
            float yf = __shfl_up_sync(0xFFFFFFFFu, xf, d);
            float yb = __shfl_up_sync(0xFFFFFFFFu, xb, d);
            if (lane >= d) { xf += yf; xb += yb; }
        }
        if (lane == 31) { wredf[wid] = xf; wredb[wid] = xb; }
        __syncthreads();
        if (wid == 0) {
            float wf = wredf[lane], wb = wredb[lane];
#pragma unroll
            for (int d = 1; d < 32; d <<= 1) {
                float yf = __shfl_up_sync(0xFFFFFFFFu, wf, d);
                float yb = __shfl_up_sync(0xFFFFFFFFu, wb, d);
                if (lane >= d) { wf += yf; wb += yb; }
            }
            wredf[lane] = wf; wredb[lane] = wb;
        }
        __syncthreads();
        float offf = (xf - tf) + (wid > 0 ? wredf[wid - 1] : 0.0f);
        float offb = (xb - tb) + (wid > 0 ? wredb[wid - 1] : 0.0f);
#pragma unroll
        for (int j = 0; j < CH; j++) {
            qf[pidx(base + j)] = offf + qfv[j];
            qb[pidx(base + j)] = offb + qbv[j];
        }
    }
    __syncthreads();

    // ---- Phase D: channel 0 (windows), strided, coalesced, division-free ----
    const float bI = invZ1;
    const float kI = k * invZ1;
#pragma unroll
    for (int ii = 0; ii < CH; ii++) {
        int t = ii * NT + tid;
        float bv = bcd[ii];
        float wfv = ((t >= 16) ? qf[pidx(t - 16)] : 0.0f)
                  - ((t >= 76) ? qf[pidx(t - 76)] : 0.0f);
        int hi = t + 75; if (hi > L - 1) hi = L - 1;
        int lo = t + 15; if (lo > L - 1) lo = L - 1;
        float wbv = qb[pidx(hi)] - qb[pidx(lo)];
        float w = wfv + wbv;
        float o = fmaf(bv * kI, w, bv * bI);         // b>eps fast path
        if (!(bv > 1e-13f)) {
            float t0 = fmaf(k, w, 1.0f);
            o = (bv * bv * t0) / (bv + 1.0f) * invZ1;
        }
        outb[t] = clip01(o);
    }
}

extern "C" void kernel_launch(void* const* d_in, const int* in_sizes, int n_in,
                              void* d_out, int out_size) {
    const float* conc = (const float*)d_in[0];
    const float* kern = (const float*)d_in[1];
    float* out = (float*)d_out;
    const int B = in_sizes[0] / (L * F);

    const size_t smem = (size_t)(2 * PL + NBUF * TFLOAT) * sizeof(float);  // 221,184 B
    cudaFuncSetAttribute(kenneth_kernel,
                         cudaFuncAttributeMaxDynamicSharedMemorySize, (int)smem);
    kenneth_kernel<<<B, NT, smem>>>(conc, kern, out);
}